// round 7
// baseline (speedup 1.0000x reference)
#include <cuda_runtime.h>
#include <math.h>
#include <stddef.h>

// Problem dims
#define TT 512
#define BB 64
#define II 256
#define HH 512
#define OO 256
#define G4 (4*HH)
#define NBLK 128
#define WPAD (HH + 4)      // padded W row stride (floats)

// ---------------- device scratch ----------------
__device__ float g_xp1[(size_t)TT*BB*G4];
__device__ float g_xp2[(size_t)BB*G4];
__device__ float g_hA[(size_t)BB*HH];
__device__ float g_hB[(size_t)BB*HH];
__device__ float g_hs2[(size_t)TT*BB*HH];
__device__ unsigned g_flags[NBLK];          // zero-init; monotonic per-block step counters

// ---------------- f32x2 / async helpers ----------------
typedef unsigned long long u64t;

__device__ __forceinline__ void fma2(u64t& acc, u64t a, u64t b) {
    asm volatile("fma.rn.f32x2 %0, %1, %2, %0;" : "+l"(acc) : "l"(a), "l"(b));
}
__device__ __forceinline__ u64t pk2(float x, float y) {
    u64t r; asm("mov.b64 %0, {%1, %2};" : "=l"(r) : "f"(x), "f"(y)); return r;
}
__device__ __forceinline__ float2 unpk2(u64t v) {
    float2 f; asm("mov.b64 {%0, %1}, %2;" : "=f"(f.x), "=f"(f.y) : "l"(v)); return f;
}
__device__ __forceinline__ void cp_async16(void* dst_smem, const void* src_gmem) {
    unsigned d = (unsigned)__cvta_generic_to_shared(dst_smem);
    asm volatile("cp.async.cg.shared.global [%0], [%1], 16;" :: "r"(d), "l"(src_gmem) : "memory");
}
__device__ __forceinline__ void st_release(unsigned* p, unsigned v) {
    asm volatile("st.global.release.gpu.u32 [%0], %1;" :: "l"(p), "r"(v) : "memory");
}
__device__ __forceinline__ unsigned ld_acquire(const unsigned* p) {
    unsigned r;
    asm volatile("ld.global.acquire.gpu.u32 %0, [%1];" : "=r"(r) : "l"(p) : "memory");
    return r;
}

// fast activations (rel err ~1e-6; tolerance is 1e-3)
__device__ __forceinline__ float fsig(float x) {
    return __fdividef(1.f, 1.f + __expf(-x));
}
__device__ __forceinline__ float ftanh(float x) {
    return __fdividef(2.f, 1.f + __expf(-2.f * x)) - 1.f;
}

// =================================================================================
// SGEMM with f32x2: C[M,N] = A[M,K] * B[N,K]^T + bias1[N] (+ bias2[N])
// =================================================================================
__global__ __launch_bounds__(256) void gemm_bias_kernel(
    const float* __restrict__ A, const float* __restrict__ B,
    const float* __restrict__ bias1, const float* __restrict__ bias2,
    float* __restrict__ C, int M, int N, int K)
{
    __shared__ float As[8][128];
    __shared__ float Bs[8][128];

    const int tid  = threadIdx.x;
    const int row0 = blockIdx.y * 128;
    const int col0 = blockIdx.x * 128;

    const int lrow = tid >> 1;
    const int lcol = (tid & 1) << 2;
    const int tr   = (tid >> 4) << 3;
    const int tc   = (tid & 15) << 3;

    u64t acc2[4][8];
    #pragma unroll
    for (int i = 0; i < 4; i++)
        #pragma unroll
        for (int j = 0; j < 8; j++) acc2[i][j] = 0ull;

    for (int k0 = 0; k0 < K; k0 += 8) {
        float4 av = make_float4(0.f, 0.f, 0.f, 0.f);
        if (row0 + lrow < M)
            av = *(const float4*)(A + (size_t)(row0 + lrow) * K + k0 + lcol);
        As[lcol+0][lrow] = av.x;
        As[lcol+1][lrow] = av.y;
        As[lcol+2][lrow] = av.z;
        As[lcol+3][lrow] = av.w;

        float4 bv = *(const float4*)(B + (size_t)(col0 + lrow) * K + k0 + lcol);
        Bs[lcol+0][lrow] = bv.x;
        Bs[lcol+1][lrow] = bv.y;
        Bs[lcol+2][lrow] = bv.z;
        Bs[lcol+3][lrow] = bv.w;

        __syncthreads();

        #pragma unroll
        for (int kk = 0; kk < 8; kk++) {
            ulonglong2 raA = *(const ulonglong2*)&As[kk][tr];
            ulonglong2 raB = *(const ulonglong2*)&As[kk][tr + 4];
            float rb[8];
            *(float4*)(rb)     = *(const float4*)&Bs[kk][tc];
            *(float4*)(rb + 4) = *(const float4*)&Bs[kk][tc + 4];
            u64t rbd[8];
            #pragma unroll
            for (int j = 0; j < 8; j++) rbd[j] = pk2(rb[j], rb[j]);
            #pragma unroll
            for (int j = 0; j < 8; j++) {
                fma2(acc2[0][j], raA.x, rbd[j]);
                fma2(acc2[1][j], raA.y, rbd[j]);
                fma2(acc2[2][j], raB.x, rbd[j]);
                fma2(acc2[3][j], raB.y, rbd[j]);
            }
        }
        __syncthreads();
    }

    float bsum[8];
    #pragma unroll
    for (int j = 0; j < 8; j++) {
        float b = bias1 ? bias1[col0 + tc + j] : 0.f;
        if (bias2) b += bias2[col0 + tc + j];
        bsum[j] = b;
    }

    #pragma unroll
    for (int i2 = 0; i2 < 4; i2++) {
        #pragma unroll
        for (int half = 0; half < 2; half++) {
            int r = row0 + tr + i2 * 2 + half;
            if (r < M) {
                #pragma unroll
                for (int j = 0; j < 8; j += 4) {
                    float4 o;
                    float2 u0 = unpk2(acc2[i2][j+0]);
                    float2 u1 = unpk2(acc2[i2][j+1]);
                    float2 u2 = unpk2(acc2[i2][j+2]);
                    float2 u3 = unpk2(acc2[i2][j+3]);
                    o.x = (half ? u0.y : u0.x) + bsum[j+0];
                    o.y = (half ? u1.y : u1.x) + bsum[j+1];
                    o.z = (half ? u2.y : u2.x) + bsum[j+2];
                    o.w = (half ? u3.y : u3.x) + bsum[j+3];
                    *(float4*)(C + (size_t)r * N + col0 + tc + j) = o;
                }
            }
        }
    }
}

// =================================================================================
// Persistent LSTM layer. 128 blocks x 256 threads (8 warps).
// Block owns JT=4 hidden cols (16 gate rows) x 64 batches.
// Warp layout: bg=tid&7 (8 batches), jj=(tid>>3)&3, ks=tid>>5 (8 k-slices of 64 k).
// PER-WARP h staging: warp ks cp.asyncs ONLY its own k-slice (64 batches x 16 float4
// = 16KB) into a private smem region, waits with per-thread cp.async semantics +
// __syncwarp, then computes. All 8 warps compute concurrently (single phase).
// Swizzle: region[b*16 + (k4l ^ (b>>3))] -> conflict-free stores AND loads.
// Tail layout: 1 cell per thread: cb=tid>>2 (batch), jz=tid&3 (col).
// =================================================================================
#define JT 4
#define RED4 2048
#define STEP_SMEM_FLOATS (32768 + 16*WPAD + RED4*4)
#define STEP_SMEM_BYTES  (STEP_SMEM_FLOATS * 4)       // 196,864 B

__global__ __launch_bounds__(256, 1) void lstm_persist_kernel(
    const float* __restrict__ h0, const float* __restrict__ c0,
    float* __restrict__ hA, float* __restrict__ hB,
    const float* __restrict__ W, const float* __restrict__ xp,
    long long xp_t_stride, float* __restrict__ hs_out)
{
    extern __shared__ float smem[];
    float4* hS4  = (float4*)smem;                     // 8 warp regions x 1024 float4
    float*  wS   = smem + 32768;                      // 16 rows x WPAD
    float4* red4 = (float4*)(smem + 32768 + 16*WPAD); // 2048 float4 partials

    const int tid  = threadIdx.x;
    const int lane = tid & 31;
    const int bg   = tid & 7;
    const int jj   = (tid >> 3) & 3;
    const int ks   = tid >> 5;
    const int jj0  = blockIdx.x * JT;

    // ---- stage W once ----
    for (int idx = tid; idx < 16 * (HH/4); idx += 256) {
        int r  = idx >> 7;
        int c4 = idx & 127;
        int g  = r >> 2, j = r & 3;
        *(float4*)(wS + r * WPAD + c4 * 4) =
            ((const float4*)(W + (size_t)(g * HH + jj0 + j) * HH))[c4];
    }

    // ---- per-thread persistent cell state (1 cell per thread) ----
    const int cb = tid >> 2, jz = tid & 3;
    const int jg = jj0 + jz;
    float creg = c0[(size_t)cb * HH + jg];

    // ---- barrier generation base ----
    unsigned base;
    {
        __shared__ unsigned s_base;
        if (tid == 0) s_base = g_flags[blockIdx.x];
        __syncthreads();
        base = s_base;
    }

    const int b0 = bg << 3;
    const float* w0 = wS + (0*4 + jj) * WPAD;
    const float* w1 = wS + (1*4 + jj) * WPAD;
    const float* w2 = wS + (2*4 + jj) * WPAD;
    const float* w3 = wS + (3*4 + jj) * WPAD;
    float4* hW = hS4 + ks * 1024;                     // this warp's private region

    for (int t = 0; t < TT; t++) {
        const float* hsrc = (t == 0) ? h0 : ((t & 1) ? hB : hA);
        float*       hdst = (t & 1) ? hA : hB;

        // ---- prefetch xp gate inputs (longest latency; consumed in tail) ----
        const float* xt = xp + (size_t)(xp_t_stride * t) + (size_t)cb * G4 + jg;
        float xi = xt[0*HH];
        float xf = xt[1*HH];
        float xg = xt[2*HH];
        float xo = xt[3*HH];

        // ---- per-warp h staging: own k-slice only, no block sync ----
        {
            const float4* hg = (const float4*)hsrc;   // [b][k4global]
            #pragma unroll 8
            for (int r = 0; r < 32; r++) {
                int flat = r * 32 + lane;             // 0..1023
                int b    = flat >> 4;
                int k4l  = flat & 15;
                cp_async16(hW + b * 16 + (k4l ^ (b >> 3)),
                           hg + b * 128 + ks * 16 + k4l);
            }
            asm volatile("cp.async.commit_group;" ::: "memory");
            asm volatile("cp.async.wait_group 0;" ::: "memory");
            __syncwarp();
        }

        // ---- single-phase compute: all 8 warps concurrent ----
        u64t acc2[8][4];
        #pragma unroll
        for (int i = 0; i < 8; i++)
            #pragma unroll
            for (int g = 0; g < 4; g++) acc2[i][g] = 0ull;

        #pragma unroll 4
        for (int it = 0; it < 16; it++) {
            int k4 = ks * 16 + it;
            ulonglong2 wv0 = *(const ulonglong2*)(w0 + k4 * 4);
            ulonglong2 wv1 = *(const ulonglong2*)(w1 + k4 * 4);
            ulonglong2 wv2 = *(const ulonglong2*)(w2 + k4 * 4);
            ulonglong2 wv3 = *(const ulonglong2*)(w3 + k4 * 4);
            #pragma unroll
            for (int i = 0; i < 8; i++) {
                ulonglong2 hv = *(const ulonglong2*)(hW + (b0 + i) * 16 + (it ^ bg));
                fma2(acc2[i][0], hv.x, wv0.x); fma2(acc2[i][0], hv.y, wv0.y);
                fma2(acc2[i][1], hv.x, wv1.x); fma2(acc2[i][1], hv.y, wv1.y);
                fma2(acc2[i][2], hv.x, wv2.x); fma2(acc2[i][2], hv.y, wv2.y);
                fma2(acc2[i][3], hv.x, wv3.x); fma2(acc2[i][3], hv.y, wv3.y);
            }
        }

        // ---- write partials (swizzled) ----
        #pragma unroll
        for (int i = 0; i < 8; i++) {
            float2 a0 = unpk2(acc2[i][0]);
            float2 a1 = unpk2(acc2[i][1]);
            float2 a2 = unpk2(acc2[i][2]);
            float2 a3 = unpk2(acc2[i][3]);
            red4[tid * 8 + (i ^ (tid & 7))] =
                make_float4(a0.x + a0.y, a1.x + a1.y, a2.x + a2.y, a3.x + a3.y);
        }
        __syncthreads();

        // ---- tail: every thread owns one (batch, col) cell ----
        {
            float4 s = make_float4(0.f, 0.f, 0.f, 0.f);
            const int cgg = cb >> 3, ii = cb & 7;
            #pragma unroll
            for (int k = 0; k < 8; k++) {
                int p = k * 32 + jz * 8 + cgg;
                float4 q = red4[p * 8 + (ii ^ (p & 7))];
                s.x += q.x; s.y += q.y; s.z += q.z; s.w += q.w;
            }
            float gi = fsig (s.x + xi);
            float gf = fsig (s.y + xf);
            float gg = ftanh(s.z + xg);
            float go = fsig (s.w + xo);
            float cn = gf * creg + gi * gg;
            creg = cn;
            float hn = go * ftanh(cn);
            hdst[(size_t)cb * HH + jg] = hn;
            if (hs_out)
                hs_out[(size_t)t * BB * HH + (size_t)cb * HH + jg] = hn;
        }

        // ---- flag-array grid barrier (parallel release-detect) ----
        if (t != TT - 1) {
            unsigned target = base + (unsigned)t + 1u;
            __syncthreads();                            // all h stores done
            if (tid == 0) st_release(&g_flags[blockIdx.x], target);
            if (tid < NBLK) {
                const unsigned* fp = &g_flags[tid];
                while ((int)(ld_acquire(fp) - target) < 0) { }
            }
            __syncthreads();
        }
    }
}

// =================================================================================
// Host launch — 5 graph nodes
// =================================================================================
extern "C" void kernel_launch(void* const* d_in, const int* in_sizes, int n_in,
                              void* d_out, int out_size)
{
    (void)in_sizes; (void)n_in; (void)out_size;
    const float* inputs = (const float*)d_in[0];
    const float* W_ih1  = (const float*)d_in[1];
    const float* W_hh1  = (const float*)d_in[2];
    const float* b_ih1  = (const float*)d_in[3];
    const float* b_hh1  = (const float*)d_in[4];
    const float* W_ih2  = (const float*)d_in[5];
    const float* W_hh2  = (const float*)d_in[6];
    const float* b_ih2  = (const float*)d_in[7];
    const float* b_hh2  = (const float*)d_in[8];
    const float* W_lin  = (const float*)d_in[9];
    const float* b_lin  = (const float*)d_in[10];
    const float* h1_0   = (const float*)d_in[11];
    const float* c1_0   = (const float*)d_in[12];
    const float* h2_0   = (const float*)d_in[13];
    const float* c2_0   = (const float*)d_in[14];
    float* out = (float*)d_out;

    float *xp1, *xp2, *hA, *hB, *hs2;
    cudaGetSymbolAddress((void**)&xp1, g_xp1);
    cudaGetSymbolAddress((void**)&xp2, g_xp2);
    cudaGetSymbolAddress((void**)&hA,  g_hA);
    cudaGetSymbolAddress((void**)&hB,  g_hB);
    cudaGetSymbolAddress((void**)&hs2, g_hs2);

    cudaFuncSetAttribute(lstm_persist_kernel,
                         cudaFuncAttributeMaxDynamicSharedMemorySize,
                         STEP_SMEM_BYTES);

    // xp1 = inputs @ W_ih1^T + b_ih1 + b_hh1
    gemm_bias_kernel<<<dim3(G4/128, (TT*BB)/128), 256>>>(
        inputs, W_ih1, b_ih1, b_hh1, xp1, TT*BB, G4, II);

    // Layer 1 (final h1T lands in hA: t=511 odd -> hA)
    lstm_persist_kernel<<<NBLK, 256, STEP_SMEM_BYTES>>>(
        h1_0, c1_0, hA, hB, W_hh1, xp1, (long long)BB * G4, nullptr);

    // xp2 = h1T @ W_ih2^T + b_ih2 + b_hh2
    gemm_bias_kernel<<<dim3(G4/128, 1), 256>>>(
        hA, W_ih2, b_ih2, b_hh2, xp2, BB, G4, HH);

    // Layer 2
    lstm_persist_kernel<<<NBLK, 256, STEP_SMEM_BYTES>>>(
        h2_0, c2_0, hA, hB, W_hh2, xp2, 0LL, hs2);

    // out = hs2 @ W_lin^T + b_lin
    gemm_bias_kernel<<<dim3(OO/128, (TT*BB)/128), 256>>>(
        hs2, W_lin, b_lin, nullptr, out, TT*BB, OO, HH);
}

// round 8
// speedup vs baseline: 1.0393x; 1.0393x over previous
#include <cuda_runtime.h>
#include <math.h>
#include <stddef.h>

// Problem dims
#define TT 512
#define BB 64
#define II 256
#define HH 512
#define OO 256
#define G4 (4*HH)
#define NBLK 128
#define JT 4                 // hidden cols per block

// ---------------- device scratch ----------------
__device__ float g_xp1[(size_t)TT*BB*G4];
__device__ float g_xp2[(size_t)BB*G4];
__device__ float g_hT[2][(size_t)HH*BB];    // transposed h, double-buffered (version v in buf v&1)
__device__ float g_hA[(size_t)BB*HH];       // layer-1 final h (batch-major, for xp2 GEMM)
__device__ float g_hs2[(size_t)TT*BB*HH];
__device__ unsigned g_flags[NBLK];          // zero-init; monotonic per-block version counters

// ---------------- helpers ----------------
typedef unsigned long long u64t;

__device__ __forceinline__ void fma2(u64t& acc, u64t a, u64t b) {
    asm volatile("fma.rn.f32x2 %0, %1, %2, %0;" : "+l"(acc) : "l"(a), "l"(b));
}
__device__ __forceinline__ u64t pk2(float x, float y) {
    u64t r; asm("mov.b64 %0, {%1, %2};" : "=l"(r) : "f"(x), "f"(y)); return r;
}
__device__ __forceinline__ float2 unpk2(u64t v) {
    float2 f; asm("mov.b64 {%0, %1}, %2;" : "=f"(f.x), "=f"(f.y) : "l"(v)); return f;
}
__device__ __forceinline__ void cp_async16(void* dst_smem, const void* src_gmem) {
    unsigned d = (unsigned)__cvta_generic_to_shared(dst_smem);
    asm volatile("cp.async.cg.shared.global [%0], [%1], 16;" :: "r"(d), "l"(src_gmem) : "memory");
}
__device__ __forceinline__ void st_release(unsigned* p, unsigned v) {
    asm volatile("st.global.release.gpu.u32 [%0], %1;" :: "l"(p), "r"(v) : "memory");
}
__device__ __forceinline__ unsigned ld_acquire(const unsigned* p) {
    unsigned r;
    asm volatile("ld.global.acquire.gpu.u32 %0, [%1];" : "=r"(r) : "l"(p) : "memory");
    return r;
}
__device__ __forceinline__ float fsig(float x)  { return __fdividef(1.f, 1.f + __expf(-x)); }
__device__ __forceinline__ float ftanh(float x) { return __fdividef(2.f, 1.f + __expf(-2.f*x)) - 1.f; }

// =================================================================================
// SGEMM with f32x2 (unchanged from best passing version)
// =================================================================================
__global__ __launch_bounds__(256) void gemm_bias_kernel(
    const float* __restrict__ A, const float* __restrict__ B,
    const float* __restrict__ bias1, const float* __restrict__ bias2,
    float* __restrict__ C, int M, int N, int K)
{
    __shared__ float As[8][128];
    __shared__ float Bs[8][128];

    const int tid  = threadIdx.x;
    const int row0 = blockIdx.y * 128;
    const int col0 = blockIdx.x * 128;

    const int lrow = tid >> 1;
    const int lcol = (tid & 1) << 2;
    const int tr   = (tid >> 4) << 3;
    const int tc   = (tid & 15) << 3;

    u64t acc2[4][8];
    #pragma unroll
    for (int i = 0; i < 4; i++)
        #pragma unroll
        for (int j = 0; j < 8; j++) acc2[i][j] = 0ull;

    for (int k0 = 0; k0 < K; k0 += 8) {
        float4 av = make_float4(0.f, 0.f, 0.f, 0.f);
        if (row0 + lrow < M)
            av = *(const float4*)(A + (size_t)(row0 + lrow) * K + k0 + lcol);
        As[lcol+0][lrow] = av.x;
        As[lcol+1][lrow] = av.y;
        As[lcol+2][lrow] = av.z;
        As[lcol+3][lrow] = av.w;

        float4 bv = *(const float4*)(B + (size_t)(col0 + lrow) * K + k0 + lcol);
        Bs[lcol+0][lrow] = bv.x;
        Bs[lcol+1][lrow] = bv.y;
        Bs[lcol+2][lrow] = bv.z;
        Bs[lcol+3][lrow] = bv.w;

        __syncthreads();

        #pragma unroll
        for (int kk = 0; kk < 8; kk++) {
            ulonglong2 raA = *(const ulonglong2*)&As[kk][tr];
            ulonglong2 raB = *(const ulonglong2*)&As[kk][tr + 4];
            float rb[8];
            *(float4*)(rb)     = *(const float4*)&Bs[kk][tc];
            *(float4*)(rb + 4) = *(const float4*)&Bs[kk][tc + 4];
            u64t rbd[8];
            #pragma unroll
            for (int j = 0; j < 8; j++) rbd[j] = pk2(rb[j], rb[j]);
            #pragma unroll
            for (int j = 0; j < 8; j++) {
                fma2(acc2[0][j], raA.x, rbd[j]);
                fma2(acc2[1][j], raA.y, rbd[j]);
                fma2(acc2[2][j], raB.x, rbd[j]);
                fma2(acc2[3][j], raB.y, rbd[j]);
            }
        }
        __syncthreads();
    }

    float bsum[8];
    #pragma unroll
    for (int j = 0; j < 8; j++) {
        float b = bias1 ? bias1[col0 + tc + j] : 0.f;
        if (bias2) b += bias2[col0 + tc + j];
        bsum[j] = b;
    }

    #pragma unroll
    for (int i2 = 0; i2 < 4; i2++) {
        #pragma unroll
        for (int half = 0; half < 2; half++) {
            int r = row0 + tr + i2 * 2 + half;
            if (r < M) {
                #pragma unroll
                for (int j = 0; j < 8; j += 4) {
                    float4 o;
                    float2 u0 = unpk2(acc2[i2][j+0]);
                    float2 u1 = unpk2(acc2[i2][j+1]);
                    float2 u2 = unpk2(acc2[i2][j+2]);
                    float2 u3 = unpk2(acc2[i2][j+3]);
                    o.x = (half ? u0.y : u0.x) + bsum[j+0];
                    o.y = (half ? u1.y : u1.x) + bsum[j+1];
                    o.z = (half ? u2.y : u2.x) + bsum[j+2];
                    o.w = (half ? u3.y : u3.x) + bsum[j+3];
                    *(float4*)(C + (size_t)r * N + col0 + tc + j) = o;
                }
            }
        }
    }
}

// =================================================================================
// Persistent LSTM layer with producer/consumer dataflow (NO global barrier).
//
// h stored transposed: hT[col][batch], double-buffered. Block p produces cols
// [4p,4p+4) (1KB contiguous) and publishes flag[p]=version. Warp ks consumes
// k in [64ks, 64ks+64) = producers [16ks,16ks+16), in 4 chunks of 4 producers,
// order staggered by blockIdx, depth-2 cp.async pipeline.
//
// Compute: lane = bg(0..7) x jj(0..3). Thread covers batches {4bg..4bg+3} u
// {32+4bg..32+4bg+3}, 4 gates, f32x2-packed along batch pairs.
// Tail: 1 cell/thread: cb=tid>>2 (batch), jz=tid&3 (col).
// =================================================================================
#define HW_FLOATS (8*64*64)                     // 8 warp regions x 64k x 64b
#define WT_FLOATS (HH*16)                       // wT[k][jj*4+g]
#define RED4 2048
#define STEP_SMEM_FLOATS (HW_FLOATS + WT_FLOATS + RED4*4)
#define STEP_SMEM_BYTES  (STEP_SMEM_FLOATS * 4) // 196,608 B

__device__ __forceinline__ void wait_chunk_flags(const unsigned* fbase, unsigned target) {
    // all lanes poll all 4 producer flags of the chunk (MLP-overlapped)
    for (;;) {
        unsigned f0 = ld_acquire(fbase + 0);
        unsigned f1 = ld_acquire(fbase + 1);
        unsigned f2 = ld_acquire(fbase + 2);
        unsigned f3 = ld_acquire(fbase + 3);
        if ((int)(f0 - target) >= 0 && (int)(f1 - target) >= 0 &&
            (int)(f2 - target) >= 0 && (int)(f3 - target) >= 0) break;
    }
    __syncwarp();
}

__global__ __launch_bounds__(256, 1) void lstm_persist_kernel(
    const float* __restrict__ h0, const float* __restrict__ c0,
    float* __restrict__ h_final,
    const float* __restrict__ W, const float* __restrict__ xp,
    long long xp_t_stride, float* __restrict__ hs_out)
{
    extern __shared__ float smem[];
    float*  hWs  = smem;                          // 8 x (64k x 64b)
    float*  wT   = smem + HW_FLOATS;              // [512][16]
    float4* red4 = (float4*)(smem + HW_FLOATS + WT_FLOATS);

    const int tid  = threadIdx.x;
    const int lane = tid & 31;
    const int warp = tid >> 5;                    // k-slice id (0..7)
    const int bg   = lane & 7;
    const int jj   = lane >> 3;
    const int jj0  = blockIdx.x * JT;

    // ---- stage W transposed once: wT[k][jj*4+g] = W[g*HH + jj0+jj][k] ----
    for (int idx = tid; idx < WT_FLOATS; idx += 256) {
        int k = idx >> 4, r = idx & 15;
        int jjr = r >> 2, g = r & 3;
        wT[idx] = W[(size_t)(g * HH + jj0 + jjr) * HH + k];
    }

    // ---- tail cell state: 1 cell per thread ----
    const int cb = tid >> 2, jz = tid & 3;
    const int jg = jj0 + jz;
    float creg = c0[(size_t)cb * HH + jg];

    // ---- barrier/version base ----
    unsigned base;
    {
        __shared__ unsigned sb;
        if (tid == 0) sb = g_flags[blockIdx.x];
        __syncthreads();
        base = sb;
    }

    // ---- initial publish: version 1 (h0 transposed) -> buf 1 ----
    {
        int b = tid & 63, r = tid >> 6;
        g_hT[1][(size_t)(jj0 + r) * BB + b] = h0[(size_t)b * HH + jj0 + r];
    }
    __syncthreads();
    if (tid == 0) st_release(&g_flags[blockIdx.x], base + 1u);

    float* hWp = hWs + warp * (64 * 64);          // this warp's k-slice region
    const float* wTw = wT + warp * 64 * 16;       // this warp's W k-slice

    int corder[4];
    #pragma unroll
    for (int i = 0; i < 4; i++) corder[i] = (int)((blockIdx.x + i) & 3);

    for (int t = 0; t < TT; t++) {
        // ---- xp prefetch (DRAM; consumed in tail) ----
        const float* xt = xp + (size_t)(xp_t_stride * t) + (size_t)cb * G4 + jg;
        float xi = xt[0*HH];
        float xf = xt[1*HH];
        float xg = xt[2*HH];
        float xo = xt[3*HH];

        const float4* hTsrc = (const float4*)(g_hT[(t + 1) & 1]);
        const unsigned target = base + (unsigned)t + 1u;

        u64t acc2[4][4];
        #pragma unroll
        for (int p = 0; p < 4; p++)
            #pragma unroll
            for (int g = 0; g < 4; g++) acc2[p][g] = 0ull;

        // ---- prologue: wait + issue first chunk ----
        {
            int c = corder[0];
            wait_chunk_flags(&g_flags[warp * 16 + c * 4], target);
            const float4* src = hTsrc + (warp * 64 + c * 16) * 16;
            float4* dst = (float4*)hWp + c * 16 * 16;
            #pragma unroll
            for (int it = 0; it < 8; it++) {
                int idx = it * 32 + lane;
                cp_async16(dst + idx, src + idx);
            }
            asm volatile("cp.async.commit_group;" ::: "memory");
        }

        // ---- pipelined chunk loop ----
        #pragma unroll
        for (int ci = 0; ci < 4; ci++) {
            if (ci < 3) {
                int cn = corder[ci + 1];
                wait_chunk_flags(&g_flags[warp * 16 + cn * 4], target);
                const float4* src = hTsrc + (warp * 64 + cn * 16) * 16;
                float4* dst = (float4*)hWp + cn * 16 * 16;
                #pragma unroll
                for (int it = 0; it < 8; it++) {
                    int idx = it * 32 + lane;
                    cp_async16(dst + idx, src + idx);
                }
                asm volatile("cp.async.commit_group;" ::: "memory");
                asm volatile("cp.async.wait_group 1;" ::: "memory");
            } else {
                asm volatile("cp.async.wait_group 0;" ::: "memory");
            }
            __syncwarp();

            // compute chunk corder[ci]: 16 k values
            const int c = corder[ci];
            #pragma unroll 8
            for (int kk = 0; kk < 16; kk++) {
                int kl = c * 16 + kk;
                float4 wv = *(const float4*)(wTw + kl * 16 + jj * 4);
                u64t d0 = pk2(wv.x, wv.x);
                u64t d1 = pk2(wv.y, wv.y);
                u64t d2 = pk2(wv.z, wv.z);
                u64t d3 = pk2(wv.w, wv.w);
                ulonglong2 hp = *(const ulonglong2*)(hWp + kl * 64 + bg * 4);
                ulonglong2 hq = *(const ulonglong2*)(hWp + kl * 64 + 32 + bg * 4);
                fma2(acc2[0][0], hp.x, d0); fma2(acc2[0][1], hp.x, d1);
                fma2(acc2[0][2], hp.x, d2); fma2(acc2[0][3], hp.x, d3);
                fma2(acc2[1][0], hp.y, d0); fma2(acc2[1][1], hp.y, d1);
                fma2(acc2[1][2], hp.y, d2); fma2(acc2[1][3], hp.y, d3);
                fma2(acc2[2][0], hq.x, d0); fma2(acc2[2][1], hq.x, d1);
                fma2(acc2[2][2], hq.x, d2); fma2(acc2[2][3], hq.x, d3);
                fma2(acc2[3][0], hq.y, d0); fma2(acc2[3][1], hq.y, d1);
                fma2(acc2[3][2], hq.y, d2); fma2(acc2[3][3], hq.y, d3);
            }
        }

        // ---- write partials: entry i (0..7) = batch {i<4: 4bg+i ; else 32+4bg+(i-4)} ----
        #pragma unroll
        for (int p = 0; p < 4; p++) {
            float2 u0 = unpk2(acc2[p][0]);
            float2 u1 = unpk2(acc2[p][1]);
            float2 u2 = unpk2(acc2[p][2]);
            float2 u3 = unpk2(acc2[p][3]);
            int i0 = (p < 2) ? 2 * p : 4 + 2 * (p - 2);
            red4[tid * 8 + ( i0      ^ (tid & 7))] = make_float4(u0.x, u1.x, u2.x, u3.x);
            red4[tid * 8 + ((i0 + 1) ^ (tid & 7))] = make_float4(u0.y, u1.y, u2.y, u3.y);
        }
        __syncthreads();

        // ---- tail: one (batch, col) cell per thread ----
        {
            int bl  = (cb < 32) ? cb : cb - 32;
            int bgb = bl >> 2;
            int ib  = (bl & 3) + ((cb >= 32) ? 4 : 0);
            float4 s = make_float4(0.f, 0.f, 0.f, 0.f);
            #pragma unroll
            for (int k = 0; k < 8; k++) {
                int p = k * 32 + jz * 8 + bgb;
                float4 q = red4[p * 8 + (ib ^ (p & 7))];
                s.x += q.x; s.y += q.y; s.z += q.z; s.w += q.w;
            }
            float gi = fsig (s.x + xi);
            float gf = fsig (s.y + xf);
            float gg = ftanh(s.z + xg);
            float go = fsig (s.w + xo);
            float cn = gf * creg + gi * gg;
            creg = cn;
            float hn = go * ftanh(cn);

            if (t < TT - 1) {
                // version t+2 -> buf (t+2)&1 = t&1
                g_hT[t & 1][(size_t)jg * BB + cb] = hn;
            } else {
                h_final[(size_t)cb * HH + jg] = hn;
            }
            if (hs_out)
                hs_out[(size_t)t * BB * HH + (size_t)cb * HH + jg] = hn;
        }
        __syncthreads();     // all hT writes of this block done
        if (t < TT - 1 && tid == 0)
            st_release(&g_flags[blockIdx.x], base + (unsigned)t + 2u);
    }
}

// =================================================================================
// Host launch — 5 graph nodes
// =================================================================================
extern "C" void kernel_launch(void* const* d_in, const int* in_sizes, int n_in,
                              void* d_out, int out_size)
{
    (void)in_sizes; (void)n_in; (void)out_size;
    const float* inputs = (const float*)d_in[0];
    const float* W_ih1  = (const float*)d_in[1];
    const float* W_hh1  = (const float*)d_in[2];
    const float* b_ih1  = (const float*)d_in[3];
    const float* b_hh1  = (const float*)d_in[4];
    const float* W_ih2  = (const float*)d_in[5];
    const float* W_hh2  = (const float*)d_in[6];
    const float* b_ih2  = (const float*)d_in[7];
    const float* b_hh2  = (const float*)d_in[8];
    const float* W_lin  = (const float*)d_in[9];
    const float* b_lin  = (const float*)d_in[10];
    const float* h1_0   = (const float*)d_in[11];
    const float* c1_0   = (const float*)d_in[12];
    const float* h2_0   = (const float*)d_in[13];
    const float* c2_0   = (const float*)d_in[14];
    float* out = (float*)d_out;

    float *xp1, *xp2, *hA, *hs2;
    cudaGetSymbolAddress((void**)&xp1, g_xp1);
    cudaGetSymbolAddress((void**)&xp2, g_xp2);
    cudaGetSymbolAddress((void**)&hA,  g_hA);
    cudaGetSymbolAddress((void**)&hs2, g_hs2);

    cudaFuncSetAttribute(lstm_persist_kernel,
                         cudaFuncAttributeMaxDynamicSharedMemorySize,
                         STEP_SMEM_BYTES);

    // xp1 = inputs @ W_ih1^T + b_ih1 + b_hh1
    gemm_bias_kernel<<<dim3(G4/128, (TT*BB)/128), 256>>>(
        inputs, W_ih1, b_ih1, b_hh1, xp1, TT*BB, G4, II);

    // Layer 1: final h (batch-major) -> hA
    lstm_persist_kernel<<<NBLK, 256, STEP_SMEM_BYTES>>>(
        h1_0, c1_0, hA, W_hh1, xp1, (long long)BB * G4, nullptr);

    // xp2 = h1T @ W_ih2^T + b_ih2 + b_hh2
    gemm_bias_kernel<<<dim3(G4/128, 1), 256>>>(
        hA, W_ih2, b_ih2, b_hh2, xp2, BB, G4, HH);

    // Layer 2: hidden sequence streamed to hs2
    lstm_persist_kernel<<<NBLK, 256, STEP_SMEM_BYTES>>>(
        h2_0, c2_0, hA, W_hh2, xp2, 0LL, hs2);

    // out = hs2 @ W_lin^T + b_lin
    gemm_bias_kernel<<<dim3(OO/128, (TT*BB)/128), 256>>>(
        hs2, W_lin, b_lin, nullptr, out, TT*BB, OO, HH);
}

// round 9
// speedup vs baseline: 1.3394x; 1.2888x over previous
#include <cuda_runtime.h>
#include <math.h>
#include <stddef.h>

// Problem dims
#define TT 512
#define BB 64
#define II 256
#define HH 512
#define OO 256
#define G4 (4*HH)
#define NBLK 128
// Grouped recurrence
#define NGRP 4
#define BPG  32          // blocks per group
#define BATG 16          // batches per group
#define COLB 16          // hidden cols per block (=> 64 gate rows per block)

// ---------------- device scratch ----------------
__device__ float g_xp1[(size_t)TT*BB*G4];
__device__ float g_xp2[(size_t)BB*G4];
__device__ float g_hP[2][(size_t)BB*HH];    // ping-pong h, batch-major [b][col]
__device__ float g_hA[(size_t)BB*HH];       // layer-1 final h
__device__ float g_hs2[(size_t)TT*BB*HH];
__device__ unsigned g_flags[NBLK];          // zero-init; monotonic per-block step counters

// ---------------- helpers ----------------
typedef unsigned long long u64t;

__device__ __forceinline__ void fma2(u64t& acc, u64t a, u64t b) {
    asm volatile("fma.rn.f32x2 %0, %1, %2, %0;" : "+l"(acc) : "l"(a), "l"(b));
}
__device__ __forceinline__ u64t pk2(float x, float y) {
    u64t r; asm("mov.b64 %0, {%1, %2};" : "=l"(r) : "f"(x), "f"(y)); return r;
}
__device__ __forceinline__ float2 unpk2(u64t v) {
    float2 f; asm("mov.b64 {%0, %1}, %2;" : "=f"(f.x), "=f"(f.y) : "l"(v)); return f;
}
__device__ __forceinline__ void cp_async16(void* dst_smem, const void* src_gmem) {
    unsigned d = (unsigned)__cvta_generic_to_shared(dst_smem);
    asm volatile("cp.async.cg.shared.global [%0], [%1], 16;" :: "r"(d), "l"(src_gmem) : "memory");
}
__device__ __forceinline__ void st_release(unsigned* p, unsigned v) {
    asm volatile("st.global.release.gpu.u32 [%0], %1;" :: "l"(p), "r"(v) : "memory");
}
__device__ __forceinline__ unsigned ld_acquire(const unsigned* p) {
    unsigned r;
    asm volatile("ld.global.acquire.gpu.u32 %0, [%1];" : "=r"(r) : "l"(p) : "memory");
    return r;
}
__device__ __forceinline__ float fsig(float x)  { return __fdividef(1.f, 1.f + __expf(-x)); }
__device__ __forceinline__ float ftanh(float x) { return __fdividef(2.f, 1.f + __expf(-2.f*x)) - 1.f; }

// =================================================================================
// SGEMM with f32x2 (unchanged, passing)
// =================================================================================
__global__ __launch_bounds__(256) void gemm_bias_kernel(
    const float* __restrict__ A, const float* __restrict__ B,
    const float* __restrict__ bias1, const float* __restrict__ bias2,
    float* __restrict__ C, int M, int N, int K)
{
    __shared__ float As[8][128];
    __shared__ float Bs[8][128];

    const int tid  = threadIdx.x;
    const int row0 = blockIdx.y * 128;
    const int col0 = blockIdx.x * 128;

    const int lrow = tid >> 1;
    const int lcol = (tid & 1) << 2;
    const int tr   = (tid >> 4) << 3;
    const int tc   = (tid & 15) << 3;

    u64t acc2[4][8];
    #pragma unroll
    for (int i = 0; i < 4; i++)
        #pragma unroll
        for (int j = 0; j < 8; j++) acc2[i][j] = 0ull;

    for (int k0 = 0; k0 < K; k0 += 8) {
        float4 av = make_float4(0.f, 0.f, 0.f, 0.f);
        if (row0 + lrow < M)
            av = *(const float4*)(A + (size_t)(row0 + lrow) * K + k0 + lcol);
        As[lcol+0][lrow] = av.x;
        As[lcol+1][lrow] = av.y;
        As[lcol+2][lrow] = av.z;
        As[lcol+3][lrow] = av.w;

        float4 bv = *(const float4*)(B + (size_t)(col0 + lrow) * K + k0 + lcol);
        Bs[lcol+0][lrow] = bv.x;
        Bs[lcol+1][lrow] = bv.y;
        Bs[lcol+2][lrow] = bv.z;
        Bs[lcol+3][lrow] = bv.w;

        __syncthreads();

        #pragma unroll
        for (int kk = 0; kk < 8; kk++) {
            ulonglong2 raA = *(const ulonglong2*)&As[kk][tr];
            ulonglong2 raB = *(const ulonglong2*)&As[kk][tr + 4];
            float rb[8];
            *(float4*)(rb)     = *(const float4*)&Bs[kk][tc];
            *(float4*)(rb + 4) = *(const float4*)&Bs[kk][tc + 4];
            u64t rbd[8];
            #pragma unroll
            for (int j = 0; j < 8; j++) rbd[j] = pk2(rb[j], rb[j]);
            #pragma unroll
            for (int j = 0; j < 8; j++) {
                fma2(acc2[0][j], raA.x, rbd[j]);
                fma2(acc2[1][j], raA.y, rbd[j]);
                fma2(acc2[2][j], raB.x, rbd[j]);
                fma2(acc2[3][j], raB.y, rbd[j]);
            }
        }
        __syncthreads();
    }

    float bsum[8];
    #pragma unroll
    for (int j = 0; j < 8; j++) {
        float b = bias1 ? bias1[col0 + tc + j] : 0.f;
        if (bias2) b += bias2[col0 + tc + j];
        bsum[j] = b;
    }

    #pragma unroll
    for (int i2 = 0; i2 < 4; i2++) {
        #pragma unroll
        for (int half = 0; half < 2; half++) {
            int r = row0 + tr + i2 * 2 + half;
            if (r < M) {
                #pragma unroll
                for (int j = 0; j < 8; j += 4) {
                    float4 o;
                    float2 u0 = unpk2(acc2[i2][j+0]);
                    float2 u1 = unpk2(acc2[i2][j+1]);
                    float2 u2 = unpk2(acc2[i2][j+2]);
                    float2 u3 = unpk2(acc2[i2][j+3]);
                    o.x = (half ? u0.y : u0.x) + bsum[j+0];
                    o.y = (half ? u1.y : u1.x) + bsum[j+1];
                    o.z = (half ? u2.y : u2.x) + bsum[j+2];
                    o.w = (half ? u3.y : u3.x) + bsum[j+3];
                    *(float4*)(C + (size_t)r * N + col0 + tc + j) = o;
                }
            }
        }
    }
}

// =================================================================================
// Grouped persistent LSTM: 4 independent groups x 32 blocks.
// group = blockIdx>>5 owns batches [16g,16g+16); block ib=blockIdx&31 owns cols
// [16ib,16ib+16) => 64 gate rows (r = col_local*4 + gate). W staged once (128KB).
// Per step a block reads only its group's h slice (16 x 512 = 32KB).
// Compute: warp ks = k-slice (64 k); lane = rg(0..7) x bq(0..3);
// thread tile = 8 rows x 4 batches x 64k, f32x2 packed over k.
// Tail: 1 cell/thread: cb = tid>>4 (batch), jz = tid&15 (col).
// Group-local 32-wide flag barrier.
// =================================================================================
#define WS4   (64*128)                   // W float4 count (128KB)
#define HS4   (BATG*128)                 // h float4 count (32KB)
#define RED4N (256*8)                    // red float4 count (32KB)
#define STEP_SMEM_BYTES ((WS4 + HS4 + RED4N) * 16)   // 196,608 B

__global__ __launch_bounds__(256, 1) void lstm_persist_kernel(
    const float* __restrict__ h0, const float* __restrict__ c0,
    float* __restrict__ h_final,
    const float* __restrict__ W, const float* __restrict__ xp,
    long long xp_t_stride, float* __restrict__ hs_out)
{
    extern __shared__ float smem[];
    float4* wS4  = (float4*)smem;                       // [64 rows][128 k4] swizzled
    float4* hS4  = (float4*)smem + WS4;                 // [16 b][128 k4] swizzled
    float4* red4 = (float4*)smem + WS4 + HS4;           // [256 tid][8]

    const int tid   = threadIdx.x;
    const int lane  = tid & 31;
    const int ks    = tid >> 5;          // k-slice / warp
    const int rg    = lane >> 2;         // row group 0..7
    const int bq    = lane & 3;          // batch group 0..3
    const int group = blockIdx.x >> 5;
    const int ib    = blockIdx.x & 31;
    const int jj0   = ib * COLB;
    const int bq0   = group * BATG;

    // ---- stage W once: row r = col_local*4 + gate ----
    for (int idx = tid; idx < WS4; idx += 256) {
        int r = idx >> 7, k4 = idx & 127;
        int col = r >> 2, g = r & 3;
        wS4[r * 128 + (k4 ^ (r >> 3))] =
            ((const float4*)(W + (size_t)(g * HH + jj0 + col) * HH))[k4];
    }

    // ---- tail cell state ----
    const int cb = tid >> 4, jz = tid & 15;
    const int bglob = bq0 + cb;
    const int jglob = jj0 + jz;
    float creg = c0[(size_t)bglob * HH + jglob];

    unsigned base;
    {
        __shared__ unsigned sb;
        if (tid == 0) sb = g_flags[blockIdx.x];
        __syncthreads();
        base = sb;
    }

    const int k4beg = ks * 16;

    for (int t = 0; t < TT; t++) {
        // ---- xp prefetch (consumed in tail) ----
        const float* xt = xp + (size_t)(xp_t_stride * t) + (size_t)bglob * G4 + jglob;
        float xi = xt[0*HH];
        float xf = xt[1*HH];
        float xg = xt[2*HH];
        float xo = xt[3*HH];

        // ---- wait for group's previous-step h ----
        if (t > 0) {
            unsigned target = base + (unsigned)t;
            if (tid < BPG) {
                const unsigned* fp = &g_flags[group * BPG + tid];
                while ((int)(ld_acquire(fp) - target) < 0) { }
            }
            __syncthreads();
        }

        // ---- stage group's h slice (32KB) ----
        const float* hsrc = (t == 0) ? h0 : g_hP[(t + 1) & 1];
        for (int idx = tid; idx < HS4; idx += 256) {
            int bl = idx >> 7, k4 = idx & 127;
            cp_async16(hS4 + bl * 128 + (k4 ^ (bl >> 2)),
                       (const float4*)hsrc + (size_t)(bq0 + bl) * 128 + k4);
        }
        asm volatile("cp.async.commit_group;" ::: "memory");
        asm volatile("cp.async.wait_group 0;" ::: "memory");
        __syncthreads();

        // ---- compute: 8 rows x 4 batches x 64 k per thread ----
        u64t acc2[8][4];
        #pragma unroll
        for (int rr = 0; rr < 8; rr++)
            #pragma unroll
            for (int i = 0; i < 4; i++) acc2[rr][i] = 0ull;

        #pragma unroll 4
        for (int it = 0; it < 16; it++) {
            int k4 = k4beg + it;
            ulonglong2 wv[8];
            #pragma unroll
            for (int rr = 0; rr < 8; rr++)
                wv[rr] = *(const ulonglong2*)(wS4 + (rg * 8 + rr) * 128 + (k4 ^ rg));
            #pragma unroll
            for (int i = 0; i < 4; i++) {
                ulonglong2 hv = *(const ulonglong2*)(hS4 + (bq * 4 + i) * 128 + (k4 ^ bq));
                #pragma unroll
                for (int rr = 0; rr < 8; rr++) {
                    fma2(acc2[rr][i], hv.x, wv[rr].x);
                    fma2(acc2[rr][i], hv.y, wv[rr].y);
                }
            }
        }

        // ---- partials: per (col_off, batch) a float4 of 4 gates ----
        #pragma unroll
        for (int co = 0; co < 2; co++) {
            #pragma unroll
            for (int i = 0; i < 4; i++) {
                int p = co * 4 + i;
                float2 s0 = unpk2(acc2[co*4+0][i]);
                float2 s1 = unpk2(acc2[co*4+1][i]);
                float2 s2 = unpk2(acc2[co*4+2][i]);
                float2 s3 = unpk2(acc2[co*4+3][i]);
                red4[tid * 8 + (p ^ (tid & 7))] =
                    make_float4(s0.x+s0.y, s1.x+s1.y, s2.x+s2.y, s3.x+s3.y);
            }
        }
        __syncthreads();

        // ---- tail: one (batch, col) cell per thread ----
        {
            // cell (cb, jz): compute thread lane = rg(jz>>1)*4 + bq(cb>>2), p = (jz&1)*4 + (cb&3)
            const int tcl = (jz >> 1) * 4 + (cb >> 2);
            const int p   = (jz & 1) * 4 + (cb & 3);
            float4 s = make_float4(0.f, 0.f, 0.f, 0.f);
            #pragma unroll
            for (int k = 0; k < 8; k++) {
                int tc = k * 32 + tcl;
                float4 q = red4[tc * 8 + (p ^ (tc & 7))];
                s.x += q.x; s.y += q.y; s.z += q.z; s.w += q.w;
            }
            float gi = fsig (s.x + xi);
            float gf = fsig (s.y + xf);
            float gg = ftanh(s.z + xg);
            float go = fsig (s.w + xo);
            float cn = gf * creg + gi * gg;
            creg = cn;
            float hn = go * ftanh(cn);

            if (t < TT - 1)
                g_hP[t & 1][(size_t)bglob * HH + jglob] = hn;
            else
                h_final[(size_t)bglob * HH + jglob] = hn;
            if (hs_out)
                hs_out[(size_t)t * BB * HH + (size_t)bglob * HH + jglob] = hn;
        }
        __syncthreads();     // block's h writes complete before release
        if (t < TT - 1 && tid == 0)
            st_release(&g_flags[blockIdx.x], base + (unsigned)t + 1u);
    }
}

// =================================================================================
// Host launch — 5 graph nodes
// =================================================================================
extern "C" void kernel_launch(void* const* d_in, const int* in_sizes, int n_in,
                              void* d_out, int out_size)
{
    (void)in_sizes; (void)n_in; (void)out_size;
    const float* inputs = (const float*)d_in[0];
    const float* W_ih1  = (const float*)d_in[1];
    const float* W_hh1  = (const float*)d_in[2];
    const float* b_ih1  = (const float*)d_in[3];
    const float* b_hh1  = (const float*)d_in[4];
    const float* W_ih2  = (const float*)d_in[5];
    const float* W_hh2  = (const float*)d_in[6];
    const float* b_ih2  = (const float*)d_in[7];
    const float* b_hh2  = (const float*)d_in[8];
    const float* W_lin  = (const float*)d_in[9];
    const float* b_lin  = (const float*)d_in[10];
    const float* h1_0   = (const float*)d_in[11];
    const float* c1_0   = (const float*)d_in[12];
    const float* h2_0   = (const float*)d_in[13];
    const float* c2_0   = (const float*)d_in[14];
    float* out = (float*)d_out;

    float *xp1, *xp2, *hA, *hs2;
    cudaGetSymbolAddress((void**)&xp1, g_xp1);
    cudaGetSymbolAddress((void**)&xp2, g_xp2);
    cudaGetSymbolAddress((void**)&hA,  g_hA);
    cudaGetSymbolAddress((void**)&hs2, g_hs2);

    cudaFuncSetAttribute(lstm_persist_kernel,
                         cudaFuncAttributeMaxDynamicSharedMemorySize,
                         STEP_SMEM_BYTES);

    // xp1 = inputs @ W_ih1^T + b_ih1 + b_hh1
    gemm_bias_kernel<<<dim3(G4/128, (TT*BB)/128), 256>>>(
        inputs, W_ih1, b_ih1, b_hh1, xp1, TT*BB, G4, II);

    // Layer 1: final h (batch-major) -> hA
    lstm_persist_kernel<<<NBLK, 256, STEP_SMEM_BYTES>>>(
        h1_0, c1_0, hA, W_hh1, xp1, (long long)BB * G4, nullptr);

    // xp2 = h1T @ W_ih2^T + b_ih2 + b_hh2
    gemm_bias_kernel<<<dim3(G4/128, 1), 256>>>(
        hA, W_ih2, b_ih2, b_hh2, xp2, BB, G4, HH);

    // Layer 2: hidden sequence streamed to hs2 (h_final unused -> hA dummy)
    lstm_persist_kernel<<<NBLK, 256, STEP_SMEM_BYTES>>>(
        h2_0, c2_0, hA, W_hh2, xp2, 0LL, hs2);

    // out = hs2 @ W_lin^T + b_lin
    gemm_bias_kernel<<<dim3(OO/128, (TT*BB)/128), 256>>>(
        hs2, W_lin, b_lin, nullptr, out, TT*BB, OO, HH);
}